// round 10
// baseline (speedup 1.0000x reference)
#include <cuda_runtime.h>
#include <cuda_fp16.h>

#define HH 200
#define WW 320
#define CC 256
#define HWSZ (HH * WW)
#define RS 14
#define BINS (RS * RS)
#define RCHUNK 16

// featT: [H*W][C] fp16. g_Mg: per-pixel per-group (8 groups x 32ch) maxima,
// fp16, 16B per pixel. g_bins: per-bin maxima (ordered-uint encoded).
__device__ __align__(128) static __half g_featT[(size_t)HWSZ * CC];
__device__ __align__(128) static __half g_Mg[(size_t)HWSZ * 8];
__device__ static unsigned g_bins[BINS];

__device__ __forceinline__ unsigned enc_f(float f) {
    unsigned u = __float_as_uint(f);
    return (u & 0x80000000u) ? ~u : (u | 0x80000000u);
}
__device__ __forceinline__ float dec_f(unsigned u) {
    return __uint_as_float((u & 0x80000000u) ? (u ^ 0x80000000u) : ~u);
}
#define ENC_NEG_INF 0x007FFFFFu  // enc_f(-inf)

// Transpose feature [C][H*W] fp32 -> featT [H*W][C] fp16 (8000 independent
// blocks, 64ch x 32hw tiles). Threads 0..63 compute per-pixel 32-channel
// group maxima from the smem tile (no shuffles, no atomics). Block (0,0)
// initializes g_bins.
__global__ void transpose_kernel(const float* __restrict__ A) {
    __shared__ float tile[64][33];
    int hw0 = blockIdx.x * 32;
    int c0 = blockIdx.y * 64;
    int tx = threadIdx.x, ty = threadIdx.y;  // 32 x 8
    int t = ty * 32 + tx;

    if (blockIdx.x == 0 && blockIdx.y == 0 && t < BINS)
        g_bins[t] = ENC_NEG_INF;

#pragma unroll
    for (int j = 0; j < 64; j += 8)
        tile[ty + j][tx] = A[(size_t)(c0 + ty + j) * HWSZ + hw0 + tx];
    __syncthreads();

#pragma unroll
    for (int rr = 0; rr < 4; rr++) {
        int hwr = ty + rr * 8;
        __half2 h = __floats2half2_rn(tile[2 * tx][hwr], tile[2 * tx + 1][hwr]);
        ((__half2*)(g_featT + (size_t)(hw0 + hwr) * CC + c0))[tx] = h;
    }

    // Group maxima: thread t<64 -> (pixel t&31, subgroup t>>5); row reads are
    // conflict-free. rn is monotone so the fp16 max bounds all fp16 entries.
    if (t < 64) {
        int pix = t & 31;
        int sub = t >> 5;
        float v = __int_as_float(0xff800000);
#pragma unroll
        for (int k = 0; k < 32; k++)
            v = fmaxf(v, tile[sub * 32 + k][pix]);
        g_Mg[(size_t)(hw0 + pix) * 8 + blockIdx.y * 2 + sub] = __float2half_rn(v);
    }
}

// Warp owns (bin mn, 16-roi chunk) and loops rois SEQUENTIALLY, keeping a
// warp-wide running lower bound Lw in registers. First evaluated sample seeds
// Lw ~ max over 256 channels; group bounds (~max of 32) then prune nearly all
// later work with zero featT traffic. Scheduling-independent.
__global__ void roi_max_kernel(const float* __restrict__ rois, int R, int nch) {
    int warp = threadIdx.x >> 5;
    int lane = threadIdx.x & 31;
    int wid = blockIdx.x * (blockDim.x >> 5) + warp;
    if (wid >= BINS * nch) return;
    int mn = wid % BINS;          // consecutive wids -> different bins
    int chunk = wid / BINS;
    int m = mn / RS;
    int n = mn - m * RS;
    int g = lane >> 2;

    // Free extra seed from other chunks (may be -inf; only helps).
    float Lw = dec_f(__ldcg(&g_bins[mn]));

    int rlo = chunk * RCHUNK;
    int rhi = min(rlo + RCHUNK, R);

    for (int r = rlo; r < rhi; r++) {
        float r0 = __ldg(rois + 4 * r + 0);
        float r1 = __ldg(rois + 4 * r + 1);
        float r2 = __ldg(rois + 4 * r + 2);
        float r3 = __ldg(rois + 4 * r + 3);
        float sh = (r2 - r0) / (float)RS;
        float sw = (r3 - r1) / (float)RS;
        float yb = r0 + sh * (float)m;
        float xb = r1 + sw * (float)n;
        float ys[2] = {yb + sh * (1.0f / 3.0f), yb + sh * (2.0f / 3.0f)};
        float xs[2] = {xb + sw * (1.0f / 3.0f), xb + sw * (2.0f / 3.0f)};

#pragma unroll
        for (int pt = 0; pt < 4; pt++) {
            float y = ys[pt >> 1], x = xs[pt & 1];
            int yf = (int)floorf(y);
            int xf = (int)floorf(x);
            // clamp BEFORE weights (faithful to reference)
            int y1 = min(max(yf, 0), HH - 1);
            int y2 = min(max(yf + 1, 0), HH - 1);
            int x1 = min(max(xf, 0), WW - 1);
            int x2 = min(max(xf + 1, 0), WW - 1);
            float wxl = x - (float)x1, wxh = (float)x2 - x;
            float wyl = y - (float)y1, wyh = (float)y2 - y;
            int pix11 = y1 * WW + x1;
            int pix12 = y1 * WW + x2;
            int pix21 = y2 * WW + x1;
            int pix22 = y2 * WW + x2;

            // This lane's group bound (convex interp of corner group maxima).
            float m11 = __half2float(__ldg(&g_Mg[(size_t)pix11 * 8 + g]));
            float m12 = __half2float(__ldg(&g_Mg[(size_t)pix12 * 8 + g]));
            float m21 = __half2float(__ldg(&g_Mg[(size_t)pix21 * 8 + g]));
            float m22 = __half2float(__ldg(&g_Mg[(size_t)pix22 * 8 + g]));
            float bg = (m11 * wxh + m12 * wxl) * wyh + (m21 * wxh + m22 * wxl) * wyl;

            bool go = (bg + 1e-4f > Lw);
            if (__any_sync(0xffffffffu, go)) {
                float v = __int_as_float(0xff800000);
                if (go) {
                    const uint4* p11 = (const uint4*)(g_featT + (size_t)pix11 * CC);
                    const uint4* p12 = (const uint4*)(g_featT + (size_t)pix12 * CC);
                    const uint4* p21 = (const uint4*)(g_featT + (size_t)pix21 * CC);
                    const uint4* p22 = (const uint4*)(g_featT + (size_t)pix22 * CC);
                    uint4 A = p11[lane];
                    uint4 B = p12[lane];
                    uint4 C = p21[lane];
                    uint4 D = p22[lane];
#pragma unroll
                    for (int k = 0; k < 4; k++) {
                        float2 fa = __half22float2(*(const __half2*)(&((const unsigned*)&A)[k]));
                        float2 fb = __half22float2(*(const __half2*)(&((const unsigned*)&B)[k]));
                        float2 fc = __half22float2(*(const __half2*)(&((const unsigned*)&C)[k]));
                        float2 fd = __half22float2(*(const __half2*)(&((const unsigned*)&D)[k]));
                        float v0 = (fa.x * wxh + fb.x * wxl) * wyh + (fc.x * wxh + fd.x * wxl) * wyl;
                        float v1 = (fa.y * wxh + fb.y * wxl) * wyh + (fc.y * wxh + fd.y * wxl) * wyl;
                        v = fmaxf(v, fmaxf(v0, v1));
                    }
                }
                // Warp-reduce the new contribution and fold into Lw so the
                // NEXT pt/roi prunes against the freshest bound.
#pragma unroll
                for (int o = 16; o; o >>= 1)
                    v = fmaxf(v, __shfl_xor_sync(0xffffffffu, v, o));
                Lw = fmaxf(Lw, v);
            }
        }
    }

    if (lane == 0) atomicMax(&g_bins[mn], enc_f(Lw));
}

// Broadcast bin_max to out[R][C][14][14]. 4 warp-contiguous float4 stores per
// thread; bin index advances by 11 mod 49 per store (256 mod 49 == 11).
__global__ void bcast_kernel(float* __restrict__ out, int total4) {
    __shared__ float4 s4[49];
    int t = threadIdx.x;
    if (t < BINS) ((float*)s4)[t] = dec_f(g_bins[t]);
    __syncthreads();
    int g0 = blockIdx.x * 1024 + t;
    int mq = g0 % 49;
#pragma unroll
    for (int k = 0; k < 4; k++) {
        int g = g0 + k * 256;
        if (g < total4) ((float4*)out)[g] = s4[mq];
        mq += 11;
        if (mq >= 49) mq -= 49;
    }
}

extern "C" void kernel_launch(void* const* d_in, const int* in_sizes, int n_in,
                              void* d_out, int out_size) {
    const float* feature = (const float*)d_in[0];
    const float* rois = (const float*)d_in[1];
    int R = in_sizes[1] / 4;

    dim3 tb(32, 8);
    dim3 tg(HWSZ / 32, CC / 64);
    transpose_kernel<<<tg, tb>>>(feature);

    int nch = (R + RCHUNK - 1) / RCHUNK;
    int warps = BINS * nch;
    roi_max_kernel<<<(warps + 3) / 4, 128>>>(rois, R, nch);

    int total4 = out_size / 4;
    bcast_kernel<<<(total4 + 1023) / 1024, 256>>>((float*)d_out, total4);
}

// round 11
// speedup vs baseline: 1.5567x; 1.5567x over previous
#include <cuda_runtime.h>
#include <cuda_fp16.h>

#define HH 200
#define WW 320
#define CC 256
#define HWSZ (HH * WW)
#define RS 14
#define BINS (RS * RS)

// Scratch: transposed feature [H*W][C] fp16 (32.8 MB) + 196 bin maxima
__device__ __align__(128) static __half g_featT[(size_t)HWSZ * CC];
__device__ static unsigned g_bins[BINS];

// Monotonic float <-> uint encoding so atomicMax on unsigned == float max
__device__ __forceinline__ unsigned enc_f(float f) {
    unsigned u = __float_as_uint(f);
    return (u & 0x80000000u) ? ~u : (u | 0x80000000u);
}
__device__ __forceinline__ float dec_f(unsigned u) {
    return __uint_as_float((u & 0x80000000u) ? (u ^ 0x80000000u) : ~u);
}
#define ENC_NEG_INF 0x007FFFFFu  // enc_f(-inf)

// Transpose feature [C][H*W] fp32 -> g_featT [H*W][C] fp16.
// Tile: 64 channels x 32 hw positions. Stores are half2 (128B/warp coalesced).
// Identical to the 43.5us champion, plus block (0,0) initializes g_bins
// (saves the separate init launch; runs before roi_max by kernel ordering).
__global__ void transpose_kernel(const float* __restrict__ A) {
    __shared__ float tile[64][33];
    int hw0 = blockIdx.x * 32;
    int c0 = blockIdx.y * 64;
    int tx = threadIdx.x, ty = threadIdx.y;  // 32 x 8

    if (blockIdx.x == 0 && blockIdx.y == 0) {
        int t = ty * 32 + tx;
        if (t < BINS) g_bins[t] = ENC_NEG_INF;
    }

#pragma unroll
    for (int j = 0; j < 64; j += 8)
        tile[ty + j][tx] = A[(size_t)(c0 + ty + j) * HWSZ + hw0 + tx];
    __syncthreads();
    // warp ty handles hw rows ty, ty+8, ty+16, ty+24; lane tx = channel pair
#pragma unroll
    for (int rr = 0; rr < 4; rr++) {
        int hwr = ty + rr * 8;
        __half2 h = __floats2half2_rn(tile[2 * tx][hwr], tile[2 * tx + 1][hwr]);
        ((__half2*)(g_featT + (size_t)(hw0 + hwr) * CC + c0))[tx] = h;
    }
}

// One warp per (roi, bin). A corner row is 256 fp16 = 512B = 32 lanes x 16B:
// exactly one LDG.128 per corner per lane. fp32 math after conversion.
// Identical to the 43.5us champion.
__global__ void roi_max_kernel(const float* __restrict__ rois, int R) {
    int warp = threadIdx.x >> 5;
    int lane = threadIdx.x & 31;
    int wid = blockIdx.x * (blockDim.x >> 5) + warp;
    if (wid >= R * BINS) return;
    int r = wid / BINS;
    int mn = wid - r * BINS;
    int m = mn / RS;
    int n = mn - m * RS;

    float r0 = __ldg(rois + 4 * r + 0);
    float r1 = __ldg(rois + 4 * r + 1);
    float r2 = __ldg(rois + 4 * r + 2);
    float r3 = __ldg(rois + 4 * r + 3);
    float sh = (r2 - r0) / (float)RS;
    float sw = (r3 - r1) / (float)RS;
    float yb = r0 + sh * (float)m;
    float xb = r1 + sw * (float)n;
    const float fr0 = 1.0f / 3.0f, fr1 = 2.0f / 3.0f;
    float ys[2] = {yb + sh * fr0, yb + sh * fr1};
    float xs[2] = {xb + sw * fr0, xb + sw * fr1};

    float vmax = __int_as_float(0xff800000);  // -inf

#pragma unroll
    for (int i = 0; i < 2; i++) {
#pragma unroll
        for (int j = 0; j < 2; j++) {
            float y = ys[i], x = xs[j];
            int yf = (int)floorf(y);
            int xf = (int)floorf(x);
            // clamp BEFORE weights (faithful to reference)
            int y1 = min(max(yf, 0), HH - 1);
            int y2 = min(max(yf + 1, 0), HH - 1);
            int x1 = min(max(xf, 0), WW - 1);
            int x2 = min(max(xf + 1, 0), WW - 1);
            float wxl = x - (float)x1;   // toward x2
            float wxh = (float)x2 - x;   // toward x1
            float wyl = y - (float)y1;
            float wyh = (float)y2 - y;

            const uint4* p11 = (const uint4*)(g_featT + (size_t)(y1 * WW + x1) * CC);
            const uint4* p12 = (const uint4*)(g_featT + (size_t)(y1 * WW + x2) * CC);
            const uint4* p21 = (const uint4*)(g_featT + (size_t)(y2 * WW + x1) * CC);
            const uint4* p22 = (const uint4*)(g_featT + (size_t)(y2 * WW + x2) * CC);

            uint4 A = p11[lane];
            uint4 B = p12[lane];
            uint4 C = p21[lane];
            uint4 D = p22[lane];
#pragma unroll
            for (int k = 0; k < 4; k++) {
                float2 fa = __half22float2(*(const __half2*)(&((const unsigned*)&A)[k]));
                float2 fb = __half22float2(*(const __half2*)(&((const unsigned*)&B)[k]));
                float2 fc = __half22float2(*(const __half2*)(&((const unsigned*)&C)[k]));
                float2 fd = __half22float2(*(const __half2*)(&((const unsigned*)&D)[k]));
                float v0 = (fa.x * wxh + fb.x * wxl) * wyh + (fc.x * wxh + fd.x * wxl) * wyl;
                float v1 = (fa.y * wxh + fb.y * wxl) * wyh + (fc.y * wxh + fd.y * wxl) * wyl;
                vmax = fmaxf(vmax, fmaxf(v0, v1));
            }
        }
    }

#pragma unroll
    for (int o = 16; o; o >>= 1)
        vmax = fmaxf(vmax, __shfl_xor_sync(0xffffffffu, vmax, o));
    if (lane == 0) atomicMax(&g_bins[mn], enc_f(vmax));
}

// Broadcast bin_max to out[R][C][14][14]. Each thread does 4 warp-contiguous
// float4 stores (block tile = 1024 float4s; store k at g0 + 256k keeps every
// STG.128 512B-contiguous per warp). Bin index advances by 11 mod 49 per k
// (256 mod 49 == 11), so the modulo is computed once.
__global__ void bcast_kernel(float* __restrict__ out, int total4) {
    __shared__ float4 s4[49];
    int t = threadIdx.x;
    if (t < BINS) ((float*)s4)[t] = dec_f(g_bins[t]);
    __syncthreads();
    int g0 = blockIdx.x * 1024 + t;
    int mq = g0 % 49;
#pragma unroll
    for (int k = 0; k < 4; k++) {
        int g = g0 + k * 256;
        if (g < total4) ((float4*)out)[g] = s4[mq];
        mq += 11;
        if (mq >= 49) mq -= 49;
    }
}

extern "C" void kernel_launch(void* const* d_in, const int* in_sizes, int n_in,
                              void* d_out, int out_size) {
    const float* feature = (const float*)d_in[0];
    const float* rois = (const float*)d_in[1];
    int R = in_sizes[1] / 4;

    dim3 tb(32, 8);
    dim3 tg(HWSZ / 32, CC / 64);
    transpose_kernel<<<tg, tb>>>(feature);

    int warps = R * BINS;
    int blocks = (warps + 7) / 8;
    roi_max_kernel<<<blocks, 256>>>(rois, R);

    int total4 = out_size / 4;
    bcast_kernel<<<(total4 + 1023) / 1024, 256>>>((float*)d_out, total4);
}